// round 15
// baseline (speedup 1.0000x reference)
#include <cuda_runtime.h>
#include <cuda_fp16.h>
#include <cstdint>

// ---------------------------------------------------------------------------
// Problem constants
// ---------------------------------------------------------------------------
#define B_TOK  65536
#define IN_D   1280
#define NEXP   8
#define HID1   256
#define HID2   128
#define N_TOT  2048              // NEXP * HID1
#define KC     64                // K chunk (64 halfs = 128B rows)

// ---------------------------------------------------------------------------
// Scratch (device globals: allocation-free rule)
// ---------------------------------------------------------------------------
__device__ __half g_xh [(size_t)B_TOK * IN_D];       // x in fp16        (160 MB)
__device__ __half g_w1t[(size_t)N_TOT * IN_D];       // W1 packed [n][k] (5.2 MB)
__device__ __half g_h1 [(size_t)B_TOK * N_TOT];      // h1 fp16          (256 MB)
__device__ __half g_w2t[(size_t)NEXP * HID2 * HID1]; // W2 packed [e][n][k]

// ---------------------------------------------------------------------------
// PTX helpers (base sm_103: mma.sync + ldmatrix + cp.async)
// ---------------------------------------------------------------------------
__device__ __forceinline__ uint32_t su32(const void* p) {
    uint32_t a;
    asm("{ .reg .u64 t; cvta.to.shared.u64 t, %1; cvt.u32.u64 %0, t; }"
        : "=r"(a) : "l"(p));
    return a;
}

__device__ __forceinline__ void cpasync16(uint32_t dst, const void* src) {
    asm volatile("cp.async.cg.shared.global [%0], [%1], 16;"
                 :: "r"(dst), "l"(src) : "memory");
}
#define CP_COMMIT() asm volatile("cp.async.commit_group;" ::: "memory")
#define CP_WAIT(n)  asm volatile("cp.async.wait_group %0;" :: "n"(n) : "memory")

__device__ __forceinline__ void ldsm4(uint32_t (&r)[4], uint32_t addr) {
    asm volatile("ldmatrix.sync.aligned.m8n8.x4.shared.b16 {%0,%1,%2,%3}, [%4];"
                 : "=r"(r[0]), "=r"(r[1]), "=r"(r[2]), "=r"(r[3]) : "r"(addr));
}

__device__ __forceinline__ void mma16816(float* d, const uint32_t* a,
                                         uint32_t b0, uint32_t b1) {
    asm volatile(
        "mma.sync.aligned.m16n8k16.row.col.f32.f16.f16.f32 "
        "{%0,%1,%2,%3},{%4,%5,%6,%7},{%8,%9},{%0,%1,%2,%3};"
        : "+f"(d[0]), "+f"(d[1]), "+f"(d[2]), "+f"(d[3])
        : "r"(a[0]), "r"(a[1]), "r"(a[2]), "r"(a[3]), "r"(b0), "r"(b1));
}

// SW128(row*128+col) == row*128 + (col ^ ((row&7)<<4))  for col<128
#define SWROW(r, c) ((uint32_t)((r) * 128 + ((c) ^ (((r) & 7) << 4))))

__device__ __forceinline__ uint32_t packh(float a, float b) {
    __half2 h = __floats2half2_rn(a, b);
    return *reinterpret_cast<uint32_t*>(&h);
}

// ---------------------------------------------------------------------------
// Kernel 1: MERGED init — blocks [0,512): weight pack; [512,8704): gate + cvt
//   Independent work partitions run concurrently instead of serialized.
// ---------------------------------------------------------------------------
#define PACK_BLOCKS 512
__global__ __launch_bounds__(256) void init_kernel(
    const float* __restrict__ W1, const float* __restrict__ W2,
    const float* __restrict__ x,  const float* __restrict__ Wg,
    const float* __restrict__ bg, float* __restrict__ out) {
    const int tid = threadIdx.x;

    if (blockIdx.x < PACK_BLOCKS) {
        // ---- weight packing (grid-stride over the pack partition) ----
        const int stride = PACK_BLOCKS * 256;
        int idx = blockIdx.x * 256 + tid;
        for (int i = idx; i < N_TOT * IN_D; i += stride) {
            int n = i / IN_D, k = i % IN_D;
            g_w1t[i] = __float2half_rn(
                W1[((size_t)(n >> 8) * IN_D + k) * HID1 + (n & 255)]);
        }
        for (int i = idx; i < NEXP * HID2 * HID1; i += stride) {
            int e = i >> 15;
            int r = i & 32767;
            int n = r >> 8;           // h2  (0..127)
            int k = r & 255;          // h1  (0..255)
            g_w2t[i] = __float2half_rn(
                W2[(size_t)e * HID1 * HID2 + (size_t)k * HID2 + n]);
        }
        return;
    }

    // ---- gate (fp32, one warp per token) + x -> fp16 conversion ----
    const int warp = ((blockIdx.x - PACK_BLOCKS) * 256 + tid) >> 5;  // token
    const int lane = tid & 31;
    const float* xr = x + (size_t)warp * IN_D;
    __half* xo = g_xh + (size_t)warp * IN_D;

    float acc[NEXP];
#pragma unroll
    for (int e = 0; e < NEXP; ++e) acc[e] = 0.f;

#pragma unroll
    for (int kb = 0; kb < IN_D / 128; ++kb) {      // lanes cover 128 k per iter
        int k = kb * 128 + lane * 4;
        float4 xv = *reinterpret_cast<const float4*>(xr + k);
        uint32_t p0 = packh(xv.x, xv.y), p1 = packh(xv.z, xv.w);
        *reinterpret_cast<uint2*>(xo + k) = make_uint2(p0, p1);
        const float xs[4] = {xv.x, xv.y, xv.z, xv.w};
#pragma unroll
        for (int j = 0; j < 4; ++j) {
            float4 wa = *reinterpret_cast<const float4*>(Wg + (size_t)(k + j) * NEXP);
            float4 wb = *reinterpret_cast<const float4*>(Wg + (size_t)(k + j) * NEXP + 4);
            acc[0] += xs[j] * wa.x; acc[1] += xs[j] * wa.y;
            acc[2] += xs[j] * wa.z; acc[3] += xs[j] * wa.w;
            acc[4] += xs[j] * wb.x; acc[5] += xs[j] * wb.y;
            acc[6] += xs[j] * wb.z; acc[7] += xs[j] * wb.w;
        }
    }
#pragma unroll
    for (int e = 0; e < NEXP; ++e) {
        float v = acc[e];
        v += __shfl_xor_sync(0xFFFFFFFFu, v, 16);
        v += __shfl_xor_sync(0xFFFFFFFFu, v, 8);
        v += __shfl_xor_sync(0xFFFFFFFFu, v, 4);
        v += __shfl_xor_sync(0xFFFFFFFFu, v, 2);
        v += __shfl_xor_sync(0xFFFFFFFFu, v, 1);
        acc[e] = v + bg[e];
    }
    float m = acc[0];
#pragma unroll
    for (int e = 1; e < NEXP; ++e) m = fmaxf(m, acc[e]);
    float s = 0.f;
#pragma unroll
    for (int e = 0; e < NEXP; ++e) { acc[e] = expf(acc[e] - m); s += acc[e]; }
    float inv = 1.f / s;
    if (lane < NEXP)
        out[(size_t)B_TOK + (size_t)warp * NEXP + lane] = acc[lane] * inv;
}

// ---------------------------------------------------------------------------
// GEMM config (PROVEN 1196us R8 config): CTA 128x128, 256 thr = 8 warps (2x4),
//   warp tile 64x32, 3-stage cp.async ring (32KB/stage), 96KB/CTA, 2 CTA/SM
// ---------------------------------------------------------------------------
#define G_STAGE 32768

#define CHUNK_MMA(acc_, sS_) do {                                              \
        _Pragma("unroll")                                                      \
        for (int k16_ = 0; k16_ < 4; ++k16_) {                                 \
            const uint32_t kx_ = (uint32_t)(k16_ << 5);                        \
            const uint32_t aA_ = ((sS_) + baseA0) ^ kx_;                       \
            const uint32_t bA_ = ((sS_) + baseB0) ^ kx_;                       \
            uint32_t af_[4][4], bf_[2][4];                                     \
            ldsm4(af_[0], aA_);                                                \
            ldsm4(af_[1], aA_ + 2048u);                                        \
            ldsm4(af_[2], aA_ + 4096u);                                        \
            ldsm4(af_[3], aA_ + 6144u);                                        \
            ldsm4(bf_[0], bA_);                                                \
            ldsm4(bf_[1], bA_ + 2048u);                                        \
            _Pragma("unroll")                                                  \
            for (int mf_ = 0; mf_ < 4; ++mf_)                                  \
                _Pragma("unroll")                                              \
                for (int nf_ = 0; nf_ < 4; ++nf_)                              \
                    mma16816((acc_)[mf_][nf_], af_[mf_],                       \
                             bf_[nf_ >> 1][nf_ & 1], bf_[nf_ >> 1][2 + (nf_ & 1)]); \
        }                                                                      \
    } while (0)

// ---------------------------------------------------------------------------
// Kernel 2: GEMM1 h1 = relu(x @ W1cat + b1)   (R8-exact)
// ---------------------------------------------------------------------------
__global__ __launch_bounds__(256, 2)
void gemm1_kernel(const float* __restrict__ b1) {
    extern __shared__ char smem[];
    const uint32_t sb = su32(smem);
    const int tid = threadIdx.x, lane = tid & 31, wid = tid >> 5;
    const int m0 = blockIdx.y * 128;
    const int n0 = blockIdx.x * 128;
    const int wm = wid >> 2, wn = wid & 3;   // warp grid 2 x 4

    const int r0 = tid >> 3, c0 = tid & 7;
    const uint32_t so0 = SWROW(r0, c0 * 16);
    const __half* gA0 = g_xh  + (size_t)(m0 + r0) * IN_D + c0 * 8;
    const __half* gB0 = g_w1t + (size_t)(n0 + r0) * IN_D + c0 * 8;

#define G1_LOAD(it_, s_) do {                                                  \
        const int k0_ = (it_) * KC;                                            \
        const uint32_t sA_ = sb + (s_) * G_STAGE;                              \
        const uint32_t sB_ = sA_ + 16384;                                      \
        _Pragma("unroll")                                                      \
        for (int i_ = 0; i_ < 4; ++i_)                                         \
            cpasync16(sA_ + so0 + i_ * 4096,                                   \
                      gA0 + (size_t)i_ * 32 * IN_D + k0_);                     \
        _Pragma("unroll")                                                      \
        for (int i_ = 0; i_ < 4; ++i_)                                         \
            cpasync16(sB_ + so0 + i_ * 4096,                                   \
                      gB0 + (size_t)i_ * 32 * IN_D + k0_);                     \
        CP_COMMIT();                                                           \
    } while (0)

    float acc[4][4][4];
#pragma unroll
    for (int i = 0; i < 4; ++i)
#pragma unroll
        for (int j = 0; j < 4; ++j)
#pragma unroll
            for (int q = 0; q < 4; ++q) acc[i][j][q] = 0.f;

    const int lrow = lane & 15;
    const int lcol = (lane >> 4) * 16;
    const uint32_t baseA0 = SWROW(wm * 64 + lrow, lcol);
    const uint32_t baseB0 = 16384u + SWROW(wn * 32 + lrow, lcol);

    const int NIT = IN_D / KC;   // 20
    G1_LOAD(0, 0);
    G1_LOAD(1, 1);

    int stage = 0;
    for (int it = 0; it < NIT; ++it) {
        CP_WAIT(1);
        __syncthreads();
        if (it + 2 < NIT) {
            int s2 = stage + 2; if (s2 >= 3) s2 -= 3;
            G1_LOAD(it + 2, s2);
        } else { CP_COMMIT(); }

        const uint32_t sS = sb + stage * G_STAGE;
        CHUNK_MMA(acc, sS);
        if (++stage == 3) stage = 0;
    }
#undef G1_LOAD

    // ---- epilogue: bias + relu -> fp16 -> g_h1 ----
    float2 bias[4];
#pragma unroll
    for (int nf = 0; nf < 4; ++nf) {
        int n = n0 + wn * 32 + nf * 8 + (lane & 3) * 2;
        bias[nf] = make_float2(b1[n], b1[n + 1]);
    }
#pragma unroll
    for (int mf = 0; mf < 4; ++mf) {
        int mA = m0 + wm * 64 + mf * 16 + (lane >> 2);
        __half* row0 = g_h1 + (size_t)mA * N_TOT;
        __half* row1 = row0 + (size_t)8 * N_TOT;
#pragma unroll
        for (int nf = 0; nf < 4; ++nf) {
            int n = n0 + wn * 32 + nf * 8 + (lane & 3) * 2;
            float v0 = fmaxf(acc[mf][nf][0] + bias[nf].x, 0.f);
            float v1 = fmaxf(acc[mf][nf][1] + bias[nf].y, 0.f);
            float v2 = fmaxf(acc[mf][nf][2] + bias[nf].x, 0.f);
            float v3 = fmaxf(acc[mf][nf][3] + bias[nf].y, 0.f);
            *reinterpret_cast<uint32_t*>(row0 + n) = packh(v0, v1);
            *reinterpret_cast<uint32_t*>(row1 + n) = packh(v2, v3);
        }
    }
}

// ---------------------------------------------------------------------------
// Kernel 3: GEMM2 + layer3 + gate-weighted sum -> predictions (R8-exact)
//   CTA 128(M) x 128(N=H2); 32 chunks = 8 experts x 4 k-chunks
// ---------------------------------------------------------------------------
__global__ __launch_bounds__(256, 2)
void gemm2_kernel(const float* __restrict__ b2, const float* __restrict__ W3,
                  const float* __restrict__ b3, float* __restrict__ out) {
    extern __shared__ char smem[];
    const uint32_t sb = su32(smem);
    float* s_part = reinterpret_cast<float*>(smem + 3 * G_STAGE); // [2][128][4]
    const int tid = threadIdx.x, lane = tid & 31, wid = tid >> 5;
    const int m0 = blockIdx.x * 128;
    const int wm = wid >> 2, wn = wid & 3;   // warp grid 2 x 4

    float predv = 0.f;

    const int r0 = tid >> 3, c0 = tid & 7;
    const uint32_t so0 = SWROW(r0, c0 * 16);
    const __half* gA0 = g_h1  + (size_t)(m0 + r0) * N_TOT + c0 * 8;
    const __half* gB0 = g_w2t + (size_t)r0 * HID1 + c0 * 8;

#define G2_LOAD(c_, s_) do {                                                   \
        const uint32_t sA_ = sb + (s_) * G_STAGE;                              \
        const uint32_t sB_ = sA_ + 16384;                                      \
        const int aoff_ = (c_) * KC;               /* (4e+kb)*64 == c*64 */    \
        const int boff_ = ((c_) >> 2) * (HID2 * HID1) + ((c_) & 3) * KC;       \
        _Pragma("unroll")                                                      \
        for (int i_ = 0; i_ < 4; ++i_)                                         \
            cpasync16(sA_ + so0 + i_ * 4096,                                   \
                      gA0 + (size_t)i_ * 32 * N_TOT + aoff_);                  \
        _Pragma("unroll")                                                      \
        for (int i_ = 0; i_ < 4; ++i_)                                         \
            cpasync16(sB_ + so0 + i_ * 4096,                                   \
                      gB0 + (size_t)i_ * 32 * HID1 + boff_);                   \
        CP_COMMIT();                                                           \
    } while (0)

    const int lrow = lane & 15;
    const int lcol = (lane >> 4) * 16;
    const uint32_t baseA0 = SWROW(wm * 64 + lrow, lcol);
    const uint32_t baseB0 = 16384u + SWROW(wn * 32 + lrow, lcol);

    G2_LOAD(0, 0);
    G2_LOAD(1, 1);

    float acc[4][4][4];
    int stage = 0;

    for (int c = 0; c < 32; ++c) {
        const int e = c >> 2, kb = c & 3;
        if (kb == 0) {
#pragma unroll
            for (int i = 0; i < 4; ++i)
#pragma unroll
                for (int j = 0; j < 4; ++j)
#pragma unroll
                    for (int q = 0; q < 4; ++q) acc[i][j][q] = 0.f;
        }

        CP_WAIT(1);
        __syncthreads();
        if (c + 2 < 32) {
            int s2 = stage + 2; if (s2 >= 3) s2 -= 3;
            G2_LOAD(c + 2, s2);
        } else { CP_COMMIT(); }

        const uint32_t sS = sb + stage * G_STAGE;
        CHUNK_MMA(acc, sS);
        if (++stage == 3) stage = 0;

        if (kb == 3) {
            // relu(h2 + b2) . W3 per row -> partials (double-buffered)
            float2 b2v[4], w3v[4];
#pragma unroll
            for (int nf = 0; nf < 4; ++nf) {
                int n = e * HID2 + wn * 32 + nf * 8 + (lane & 3) * 2;
                b2v[nf] = make_float2(b2[n], b2[n + 1]);
                w3v[nf] = make_float2(W3[n], W3[n + 1]);
            }
            float* part = s_part + (e & 1) * 512;
#pragma unroll
            for (int mf = 0; mf < 4; ++mf) {
#pragma unroll
                for (int h = 0; h < 2; ++h) {
                    float s = 0.f;
#pragma unroll
                    for (int nf = 0; nf < 4; ++nf) {
                        float hv0 = fmaxf(acc[mf][nf][h * 2 + 0] + b2v[nf].x, 0.f);
                        float hv1 = fmaxf(acc[mf][nf][h * 2 + 1] + b2v[nf].y, 0.f);
                        s += hv0 * w3v[nf].x + hv1 * w3v[nf].y;
                    }
                    s += __shfl_xor_sync(0xFFFFFFFFu, s, 1);
                    s += __shfl_xor_sync(0xFFFFFFFFu, s, 2);
                    if ((lane & 3) == 0) {
                        int m_local = wm * 64 + mf * 16 + h * 8 + (lane >> 2);
                        part[m_local * 4 + wn] = s;
                    }
                }
            }
            __syncthreads();
            if (tid < 128) {
                float dot = part[tid * 4 + 0] + part[tid * 4 + 1] +
                            part[tid * 4 + 2] + part[tid * 4 + 3];
                float g = out[(size_t)B_TOK + (size_t)(m0 + tid) * NEXP + e];
                predv += g * (dot + b3[e]);
            }
            // no trailing sync: next expert uses the other part buffer, and
            // chunk-top syncs separate reuse of this one
        }
    }
#undef G2_LOAD
    if (tid < 128) out[m0 + tid] = predv;
}

// ---------------------------------------------------------------------------
// Launch
// ---------------------------------------------------------------------------
extern "C" void kernel_launch(void* const* d_in, const int* in_sizes, int n_in,
                              void* d_out, int out_size) {
    const float* x  = (const float*)d_in[0];
    const float* W1 = (const float*)d_in[1];
    const float* b1 = (const float*)d_in[2];
    const float* W2 = (const float*)d_in[3];
    const float* b2 = (const float*)d_in[4];
    const float* W3 = (const float*)d_in[5];
    const float* b3 = (const float*)d_in[6];
    const float* Wg = (const float*)d_in[7];
    const float* bg = (const float*)d_in[8];
    float* out = (float*)d_out;

    const int SMEM1 = 3 * G_STAGE;            // 98304
    const int SMEM2 = 3 * G_STAGE + 4096;     // 102400
    cudaFuncSetAttribute(gemm1_kernel, cudaFuncAttributeMaxDynamicSharedMemorySize, SMEM1);
    cudaFuncSetAttribute(gemm2_kernel, cudaFuncAttributeMaxDynamicSharedMemorySize, SMEM2);

    init_kernel<<<PACK_BLOCKS + B_TOK / 8, 256>>>(W1, W2, x, Wg, bg, out);
    gemm1_kernel<<<dim3(N_TOT / 128, B_TOK / 128), 256, SMEM1>>>(b1);
    gemm2_kernel<<<B_TOK / 128, 256, SMEM2>>>(b2, W3, b3, out);
}

// round 16
// speedup vs baseline: 1.3129x; 1.3129x over previous
#include <cuda_runtime.h>
#include <cuda_fp16.h>
#include <cstdint>

// ---------------------------------------------------------------------------
// Problem constants
// ---------------------------------------------------------------------------
#define B_TOK  65536
#define IN_D   1280
#define NEXP   8
#define HID1   256
#define HID2   128
#define N_TOT  2048              // NEXP * HID1
#define KC     64                // K chunk (64 halfs = 128B rows)

// ---------------------------------------------------------------------------
// Scratch (device globals: allocation-free rule)
// ---------------------------------------------------------------------------
__device__ __half g_xh [(size_t)B_TOK * IN_D];       // x in fp16        (160 MB)
__device__ __half g_w1t[(size_t)N_TOT * IN_D];       // W1 packed [n][k] (5.2 MB)
__device__ __half g_h1 [(size_t)B_TOK * N_TOT];      // h1 fp16          (256 MB)
__device__ __half g_w2t[(size_t)NEXP * HID2 * HID1]; // W2 packed [e][n][k]

// ---------------------------------------------------------------------------
// PTX helpers (base sm_103: mma.sync + ldmatrix + cp.async)
// ---------------------------------------------------------------------------
__device__ __forceinline__ uint32_t su32(const void* p) {
    uint32_t a;
    asm("{ .reg .u64 t; cvta.to.shared.u64 t, %1; cvt.u32.u64 %0, t; }"
        : "=r"(a) : "l"(p));
    return a;
}

__device__ __forceinline__ void cpasync16(uint32_t dst, const void* src) {
    asm volatile("cp.async.cg.shared.global [%0], [%1], 16;"
                 :: "r"(dst), "l"(src) : "memory");
}
#define CP_COMMIT() asm volatile("cp.async.commit_group;" ::: "memory")
#define CP_WAIT(n)  asm volatile("cp.async.wait_group %0;" :: "n"(n) : "memory")

__device__ __forceinline__ void ldsm4(uint32_t (&r)[4], uint32_t addr) {
    asm volatile("ldmatrix.sync.aligned.m8n8.x4.shared.b16 {%0,%1,%2,%3}, [%4];"
                 : "=r"(r[0]), "=r"(r[1]), "=r"(r[2]), "=r"(r[3]) : "r"(addr));
}

__device__ __forceinline__ void mma16816(float* d, const uint32_t* a,
                                         uint32_t b0, uint32_t b1) {
    asm volatile(
        "mma.sync.aligned.m16n8k16.row.col.f32.f16.f16.f32 "
        "{%0,%1,%2,%3},{%4,%5,%6,%7},{%8,%9},{%0,%1,%2,%3};"
        : "+f"(d[0]), "+f"(d[1]), "+f"(d[2]), "+f"(d[3])
        : "r"(a[0]), "r"(a[1]), "r"(a[2]), "r"(a[3]), "r"(b0), "r"(b1));
}

// SW128(row*128+col) == row*128 + (col ^ ((row&7)<<4))  for col<128
#define SWROW(r, c) ((uint32_t)((r) * 128 + ((c) ^ (((r) & 7) << 4))))

__device__ __forceinline__ uint32_t packh(float a, float b) {
    __half2 h = __floats2half2_rn(a, b);
    return *reinterpret_cast<uint32_t*>(&h);
}

// ---------------------------------------------------------------------------
// Kernel 1: MERGED init — blocks [0,512): weight pack; [512,8704): gate + cvt
//   Gate body is the PROVEN R8 loop: k = lane + 32*i -> Wg warp-loads touch
//   8 cache lines (32B lane stride), x reads coalesced 128B/warp.
// ---------------------------------------------------------------------------
#define PACK_BLOCKS 512
__global__ __launch_bounds__(256) void init_kernel(
    const float* __restrict__ W1, const float* __restrict__ W2,
    const float* __restrict__ x,  const float* __restrict__ Wg,
    const float* __restrict__ bg, float* __restrict__ out) {
    const int tid = threadIdx.x;

    if (blockIdx.x < PACK_BLOCKS) {
        // ---- weight packing (grid-stride over the pack partition) ----
        const int stride = PACK_BLOCKS * 256;
        int idx = blockIdx.x * 256 + tid;
        for (int i = idx; i < N_TOT * IN_D; i += stride) {
            int n = i / IN_D, k = i % IN_D;
            g_w1t[i] = __float2half_rn(
                W1[((size_t)(n >> 8) * IN_D + k) * HID1 + (n & 255)]);
        }
        for (int i = idx; i < NEXP * HID2 * HID1; i += stride) {
            int e = i >> 15;
            int r = i & 32767;
            int n = r >> 8;           // h2  (0..127)
            int k = r & 255;          // h1  (0..255)
            g_w2t[i] = __float2half_rn(
                W2[(size_t)e * HID1 * HID2 + (size_t)k * HID2 + n]);
        }
        return;
    }

    // ---- gate (fp32, one warp per token) + x -> fp16 conversion (R8-exact)
    const int warp = ((blockIdx.x - PACK_BLOCKS) * 256 + tid) >> 5;  // token
    const int lane = tid & 31;
    const float* xr = x + (size_t)warp * IN_D;
    __half* xo = g_xh + (size_t)warp * IN_D;

    float acc[NEXP];
#pragma unroll
    for (int e = 0; e < NEXP; ++e) acc[e] = 0.f;

    for (int k = lane; k < IN_D; k += 32) {
        float xv = xr[k];
        xo[k] = __float2half_rn(xv);
        float4 wa = *reinterpret_cast<const float4*>(Wg + (size_t)k * NEXP);
        float4 wb = *reinterpret_cast<const float4*>(Wg + (size_t)k * NEXP + 4);
        acc[0] += xv * wa.x; acc[1] += xv * wa.y;
        acc[2] += xv * wa.z; acc[3] += xv * wa.w;
        acc[4] += xv * wb.x; acc[5] += xv * wb.y;
        acc[6] += xv * wb.z; acc[7] += xv * wb.w;
    }
#pragma unroll
    for (int e = 0; e < NEXP; ++e) {
        float v = acc[e];
        v += __shfl_xor_sync(0xFFFFFFFFu, v, 16);
        v += __shfl_xor_sync(0xFFFFFFFFu, v, 8);
        v += __shfl_xor_sync(0xFFFFFFFFu, v, 4);
        v += __shfl_xor_sync(0xFFFFFFFFu, v, 2);
        v += __shfl_xor_sync(0xFFFFFFFFu, v, 1);
        acc[e] = v + bg[e];
    }
    float m = acc[0];
#pragma unroll
    for (int e = 1; e < NEXP; ++e) m = fmaxf(m, acc[e]);
    float s = 0.f;
#pragma unroll
    for (int e = 0; e < NEXP; ++e) { acc[e] = expf(acc[e] - m); s += acc[e]; }
    float inv = 1.f / s;
    if (lane < NEXP)
        out[(size_t)B_TOK + (size_t)warp * NEXP + lane] = acc[lane] * inv;
}

// ---------------------------------------------------------------------------
// GEMM config (PROVEN 1196us R8 config): CTA 128x128, 256 thr = 8 warps (2x4),
//   warp tile 64x32, 3-stage cp.async ring (32KB/stage), 96KB/CTA, 2 CTA/SM
// ---------------------------------------------------------------------------
#define G_STAGE 32768

#define CHUNK_MMA(acc_, sS_) do {                                              \
        _Pragma("unroll")                                                      \
        for (int k16_ = 0; k16_ < 4; ++k16_) {                                 \
            const uint32_t kx_ = (uint32_t)(k16_ << 5);                        \
            const uint32_t aA_ = ((sS_) + baseA0) ^ kx_;                       \
            const uint32_t bA_ = ((sS_) + baseB0) ^ kx_;                       \
            uint32_t af_[4][4], bf_[2][4];                                     \
            ldsm4(af_[0], aA_);                                                \
            ldsm4(af_[1], aA_ + 2048u);                                        \
            ldsm4(af_[2], aA_ + 4096u);                                        \
            ldsm4(af_[3], aA_ + 6144u);                                        \
            ldsm4(bf_[0], bA_);                                                \
            ldsm4(bf_[1], bA_ + 2048u);                                        \
            _Pragma("unroll")                                                  \
            for (int mf_ = 0; mf_ < 4; ++mf_)                                  \
                _Pragma("unroll")                                              \
                for (int nf_ = 0; nf_ < 4; ++nf_)                              \
                    mma16816((acc_)[mf_][nf_], af_[mf_],                       \
                             bf_[nf_ >> 1][nf_ & 1], bf_[nf_ >> 1][2 + (nf_ & 1)]); \
        }                                                                      \
    } while (0)

// ---------------------------------------------------------------------------
// Kernel 2: GEMM1 h1 = relu(x @ W1cat + b1)   (R8-exact)
// ---------------------------------------------------------------------------
__global__ __launch_bounds__(256, 2)
void gemm1_kernel(const float* __restrict__ b1) {
    extern __shared__ char smem[];
    const uint32_t sb = su32(smem);
    const int tid = threadIdx.x, lane = tid & 31, wid = tid >> 5;
    const int m0 = blockIdx.y * 128;
    const int n0 = blockIdx.x * 128;
    const int wm = wid >> 2, wn = wid & 3;   // warp grid 2 x 4

    const int r0 = tid >> 3, c0 = tid & 7;
    const uint32_t so0 = SWROW(r0, c0 * 16);
    const __half* gA0 = g_xh  + (size_t)(m0 + r0) * IN_D + c0 * 8;
    const __half* gB0 = g_w1t + (size_t)(n0 + r0) * IN_D + c0 * 8;

#define G1_LOAD(it_, s_) do {                                                  \
        const int k0_ = (it_) * KC;                                            \
        const uint32_t sA_ = sb + (s_) * G_STAGE;                              \
        const uint32_t sB_ = sA_ + 16384;                                      \
        _Pragma("unroll")                                                      \
        for (int i_ = 0; i_ < 4; ++i_)                                         \
            cpasync16(sA_ + so0 + i_ * 4096,                                   \
                      gA0 + (size_t)i_ * 32 * IN_D + k0_);                     \
        _Pragma("unroll")                                                      \
        for (int i_ = 0; i_ < 4; ++i_)                                         \
            cpasync16(sB_ + so0 + i_ * 4096,                                   \
                      gB0 + (size_t)i_ * 32 * IN_D + k0_);                     \
        CP_COMMIT();                                                           \
    } while (0)

    float acc[4][4][4];
#pragma unroll
    for (int i = 0; i < 4; ++i)
#pragma unroll
        for (int j = 0; j < 4; ++j)
#pragma unroll
            for (int q = 0; q < 4; ++q) acc[i][j][q] = 0.f;

    const int lrow = lane & 15;
    const int lcol = (lane >> 4) * 16;
    const uint32_t baseA0 = SWROW(wm * 64 + lrow, lcol);
    const uint32_t baseB0 = 16384u + SWROW(wn * 32 + lrow, lcol);

    const int NIT = IN_D / KC;   // 20
    G1_LOAD(0, 0);
    G1_LOAD(1, 1);

    int stage = 0;
    for (int it = 0; it < NIT; ++it) {
        CP_WAIT(1);
        __syncthreads();
        if (it + 2 < NIT) {
            int s2 = stage + 2; if (s2 >= 3) s2 -= 3;
            G1_LOAD(it + 2, s2);
        } else { CP_COMMIT(); }

        const uint32_t sS = sb + stage * G_STAGE;
        CHUNK_MMA(acc, sS);
        if (++stage == 3) stage = 0;
    }
#undef G1_LOAD

    // ---- epilogue: bias + relu -> fp16 -> g_h1 ----
    float2 bias[4];
#pragma unroll
    for (int nf = 0; nf < 4; ++nf) {
        int n = n0 + wn * 32 + nf * 8 + (lane & 3) * 2;
        bias[nf] = make_float2(b1[n], b1[n + 1]);
    }
#pragma unroll
    for (int mf = 0; mf < 4; ++mf) {
        int mA = m0 + wm * 64 + mf * 16 + (lane >> 2);
        __half* row0 = g_h1 + (size_t)mA * N_TOT;
        __half* row1 = row0 + (size_t)8 * N_TOT;
#pragma unroll
        for (int nf = 0; nf < 4; ++nf) {
            int n = n0 + wn * 32 + nf * 8 + (lane & 3) * 2;
            float v0 = fmaxf(acc[mf][nf][0] + bias[nf].x, 0.f);
            float v1 = fmaxf(acc[mf][nf][1] + bias[nf].y, 0.f);
            float v2 = fmaxf(acc[mf][nf][2] + bias[nf].x, 0.f);
            float v3 = fmaxf(acc[mf][nf][3] + bias[nf].y, 0.f);
            *reinterpret_cast<uint32_t*>(row0 + n) = packh(v0, v1);
            *reinterpret_cast<uint32_t*>(row1 + n) = packh(v2, v3);
        }
    }
}

// ---------------------------------------------------------------------------
// Kernel 3: GEMM2 + layer3 + gate-weighted sum -> predictions (R8-exact)
//   CTA 128(M) x 128(N=H2); 32 chunks = 8 experts x 4 k-chunks
// ---------------------------------------------------------------------------
__global__ __launch_bounds__(256, 2)
void gemm2_kernel(const float* __restrict__ b2, const float* __restrict__ W3,
                  const float* __restrict__ b3, float* __restrict__ out) {
    extern __shared__ char smem[];
    const uint32_t sb = su32(smem);
    float* s_part = reinterpret_cast<float*>(smem + 3 * G_STAGE); // [2][128][4]
    const int tid = threadIdx.x, lane = tid & 31, wid = tid >> 5;
    const int m0 = blockIdx.x * 128;
    const int wm = wid >> 2, wn = wid & 3;   // warp grid 2 x 4

    float predv = 0.f;

    const int r0 = tid >> 3, c0 = tid & 7;
    const uint32_t so0 = SWROW(r0, c0 * 16);
    const __half* gA0 = g_h1  + (size_t)(m0 + r0) * N_TOT + c0 * 8;
    const __half* gB0 = g_w2t + (size_t)r0 * HID1 + c0 * 8;

#define G2_LOAD(c_, s_) do {                                                   \
        const uint32_t sA_ = sb + (s_) * G_STAGE;                              \
        const uint32_t sB_ = sA_ + 16384;                                      \
        const int aoff_ = (c_) * KC;               /* (4e+kb)*64 == c*64 */    \
        const int boff_ = ((c_) >> 2) * (HID2 * HID1) + ((c_) & 3) * KC;       \
        _Pragma("unroll")                                                      \
        for (int i_ = 0; i_ < 4; ++i_)                                         \
            cpasync16(sA_ + so0 + i_ * 4096,                                   \
                      gA0 + (size_t)i_ * 32 * N_TOT + aoff_);                  \
        _Pragma("unroll")                                                      \
        for (int i_ = 0; i_ < 4; ++i_)                                         \
            cpasync16(sB_ + so0 + i_ * 4096,                                   \
                      gB0 + (size_t)i_ * 32 * HID1 + boff_);                   \
        CP_COMMIT();                                                           \
    } while (0)

    const int lrow = lane & 15;
    const int lcol = (lane >> 4) * 16;
    const uint32_t baseA0 = SWROW(wm * 64 + lrow, lcol);
    const uint32_t baseB0 = 16384u + SWROW(wn * 32 + lrow, lcol);

    G2_LOAD(0, 0);
    G2_LOAD(1, 1);

    float acc[4][4][4];
    int stage = 0;

    for (int c = 0; c < 32; ++c) {
        const int e = c >> 2, kb = c & 3;
        if (kb == 0) {
#pragma unroll
            for (int i = 0; i < 4; ++i)
#pragma unroll
                for (int j = 0; j < 4; ++j)
#pragma unroll
                    for (int q = 0; q < 4; ++q) acc[i][j][q] = 0.f;
        }

        CP_WAIT(1);
        __syncthreads();
        if (c + 2 < 32) {
            int s2 = stage + 2; if (s2 >= 3) s2 -= 3;
            G2_LOAD(c + 2, s2);
        } else { CP_COMMIT(); }

        const uint32_t sS = sb + stage * G_STAGE;
        CHUNK_MMA(acc, sS);
        if (++stage == 3) stage = 0;

        if (kb == 3) {
            // relu(h2 + b2) . W3 per row -> partials (double-buffered)
            float2 b2v[4], w3v[4];
#pragma unroll
            for (int nf = 0; nf < 4; ++nf) {
                int n = e * HID2 + wn * 32 + nf * 8 + (lane & 3) * 2;
                b2v[nf] = make_float2(b2[n], b2[n + 1]);
                w3v[nf] = make_float2(W3[n], W3[n + 1]);
            }
            float* part = s_part + (e & 1) * 512;
#pragma unroll
            for (int mf = 0; mf < 4; ++mf) {
#pragma unroll
                for (int h = 0; h < 2; ++h) {
                    float s = 0.f;
#pragma unroll
                    for (int nf = 0; nf < 4; ++nf) {
                        float hv0 = fmaxf(acc[mf][nf][h * 2 + 0] + b2v[nf].x, 0.f);
                        float hv1 = fmaxf(acc[mf][nf][h * 2 + 1] + b2v[nf].y, 0.f);
                        s += hv0 * w3v[nf].x + hv1 * w3v[nf].y;
                    }
                    s += __shfl_xor_sync(0xFFFFFFFFu, s, 1);
                    s += __shfl_xor_sync(0xFFFFFFFFu, s, 2);
                    if ((lane & 3) == 0) {
                        int m_local = wm * 64 + mf * 16 + h * 8 + (lane >> 2);
                        part[m_local * 4 + wn] = s;
                    }
                }
            }
            __syncthreads();
            if (tid < 128) {
                float dot = part[tid * 4 + 0] + part[tid * 4 + 1] +
                            part[tid * 4 + 2] + part[tid * 4 + 3];
                float g = out[(size_t)B_TOK + (size_t)(m0 + tid) * NEXP + e];
                predv += g * (dot + b3[e]);
            }
            // no trailing sync: next expert uses the other part buffer, and
            // chunk-top syncs separate reuse of this one
        }
    }
#undef G2_LOAD
    if (tid < 128) out[m0 + tid] = predv;
}

// ---------------------------------------------------------------------------
// Launch
// ---------------------------------------------------------------------------
extern "C" void kernel_launch(void* const* d_in, const int* in_sizes, int n_in,
                              void* d_out, int out_size) {
    const float* x  = (const float*)d_in[0];
    const float* W1 = (const float*)d_in[1];
    const float* b1 = (const float*)d_in[2];
    const float* W2 = (const float*)d_in[3];
    const float* b2 = (const float*)d_in[4];
    const float* W3 = (const float*)d_in[5];
    const float* b3 = (const float*)d_in[6];
    const float* Wg = (const float*)d_in[7];
    const float* bg = (const float*)d_in[8];
    float* out = (float*)d_out;

    const int SMEM1 = 3 * G_STAGE;            // 98304
    const int SMEM2 = 3 * G_STAGE + 4096;     // 102400
    cudaFuncSetAttribute(gemm1_kernel, cudaFuncAttributeMaxDynamicSharedMemorySize, SMEM1);
    cudaFuncSetAttribute(gemm2_kernel, cudaFuncAttributeMaxDynamicSharedMemorySize, SMEM2);

    init_kernel<<<PACK_BLOCKS + B_TOK / 8, 256>>>(W1, W2, x, Wg, bg, out);
    gemm1_kernel<<<dim3(N_TOT / 128, B_TOK / 128), 256, SMEM1>>>(b1);
    gemm2_kernel<<<B_TOK / 128, 256, SMEM2>>>(b2, W3, b3, out);
}

// round 17
// speedup vs baseline: 1.3711x; 1.0443x over previous
#include <cuda_runtime.h>
#include <cuda_fp16.h>
#include <cstdint>

// ---------------------------------------------------------------------------
// Problem constants
// ---------------------------------------------------------------------------
#define B_TOK  65536
#define IN_D   1280
#define NEXP   8
#define HID1   256
#define HID2   128
#define N_TOT  2048              // NEXP * HID1
#define KC     64                // K chunk (64 halfs = 128B rows)

// ---------------------------------------------------------------------------
// Scratch (device globals: allocation-free rule)
// ---------------------------------------------------------------------------
__device__ __half g_xh [(size_t)B_TOK * IN_D];       // x in fp16        (160 MB)
__device__ __half g_w1t[(size_t)N_TOT * IN_D];       // W1 packed [n][k] (5.2 MB)
__device__ __half g_h1 [(size_t)B_TOK * N_TOT];      // h1 fp16          (256 MB)
__device__ __half g_w2t[(size_t)NEXP * HID2 * HID1]; // W2 packed [e][n][k]

// ---------------------------------------------------------------------------
// PTX helpers (base sm_103: mma.sync + ldmatrix + cp.async)
// ---------------------------------------------------------------------------
__device__ __forceinline__ uint32_t su32(const void* p) {
    uint32_t a;
    asm("{ .reg .u64 t; cvta.to.shared.u64 t, %1; cvt.u32.u64 %0, t; }"
        : "=r"(a) : "l"(p));
    return a;
}

__device__ __forceinline__ void cpasync16(uint32_t dst, const void* src) {
    asm volatile("cp.async.cg.shared.global [%0], [%1], 16;"
                 :: "r"(dst), "l"(src) : "memory");
}
#define CP_COMMIT() asm volatile("cp.async.commit_group;" ::: "memory")
#define CP_WAIT(n)  asm volatile("cp.async.wait_group %0;" :: "n"(n) : "memory")

__device__ __forceinline__ void ldsm4(uint32_t (&r)[4], uint32_t addr) {
    asm volatile("ldmatrix.sync.aligned.m8n8.x4.shared.b16 {%0,%1,%2,%3}, [%4];"
                 : "=r"(r[0]), "=r"(r[1]), "=r"(r[2]), "=r"(r[3]) : "r"(addr));
}

__device__ __forceinline__ void mma16816(float* d, const uint32_t* a,
                                         uint32_t b0, uint32_t b1) {
    asm volatile(
        "mma.sync.aligned.m16n8k16.row.col.f32.f16.f16.f32 "
        "{%0,%1,%2,%3},{%4,%5,%6,%7},{%8,%9},{%0,%1,%2,%3};"
        : "+f"(d[0]), "+f"(d[1]), "+f"(d[2]), "+f"(d[3])
        : "r"(a[0]), "r"(a[1]), "r"(a[2]), "r"(a[3]), "r"(b0), "r"(b1));
}

// SW128(row*128+col) == row*128 + (col ^ (((row)&7)<<4))  for col<128
#define SWROW(r, c) ((uint32_t)((r) * 128 + ((c) ^ (((r) & 7) << 4))))

__device__ __forceinline__ uint32_t packh(float a, float b) {
    __half2 h = __floats2half2_rn(a, b);
    return *reinterpret_cast<uint32_t*>(&h);
}

// ---------------------------------------------------------------------------
// Kernel 1: MERGED init — blocks [0,512): weight pack;
//           blocks [512, 512+2048): gate + x->fp16, 4 TOKENS PER WARP
//   Wg fragment loads (16 L1 wavefronts/iter) hoisted across 4 tokens:
//   per-token L1 wavefronts drop 18 -> 6 per 32-k iteration.
// ---------------------------------------------------------------------------
#define PACK_BLOCKS 512
#define TPW 4                      // tokens per warp
__global__ __launch_bounds__(256) void init_kernel(
    const float* __restrict__ W1, const float* __restrict__ W2,
    const float* __restrict__ x,  const float* __restrict__ Wg,
    const float* __restrict__ bg, float* __restrict__ out) {
    const int tid = threadIdx.x;

    if (blockIdx.x < PACK_BLOCKS) {
        // ---- weight packing (grid-stride over the pack partition) ----
        const int stride = PACK_BLOCKS * 256;
        int idx = blockIdx.x * 256 + tid;
        for (int i = idx; i < N_TOT * IN_D; i += stride) {
            int n = i / IN_D, k = i % IN_D;
            g_w1t[i] = __float2half_rn(
                W1[((size_t)(n >> 8) * IN_D + k) * HID1 + (n & 255)]);
        }
        for (int i = idx; i < NEXP * HID2 * HID1; i += stride) {
            int e = i >> 15;
            int r = i & 32767;
            int n = r >> 8;           // h2  (0..127)
            int k = r & 255;          // h1  (0..255)
            g_w2t[i] = __float2half_rn(
                W2[(size_t)e * HID1 * HID2 + (size_t)k * HID2 + n]);
        }
        return;
    }

    // ---- gate (fp32) + x -> fp16 conversion: one warp = TPW tokens ----
    const int gwarp = ((blockIdx.x - PACK_BLOCKS) * 256 + tid) >> 5;
    const int lane = tid & 31;
    const int tok0 = gwarp * TPW;
    const float* xr0 = x    + (size_t)tok0 * IN_D;
    __half*      xo0 = g_xh + (size_t)tok0 * IN_D;

    float acc[TPW][NEXP];
#pragma unroll
    for (int t = 0; t < TPW; ++t)
#pragma unroll
        for (int e = 0; e < NEXP; ++e) acc[t][e] = 0.f;

    for (int k = lane; k < IN_D; k += 32) {
        // Wg fragment: loaded once, reused for all TPW tokens
        float4 wa = *reinterpret_cast<const float4*>(Wg + (size_t)k * NEXP);
        float4 wb = *reinterpret_cast<const float4*>(Wg + (size_t)k * NEXP + 4);
#pragma unroll
        for (int t = 0; t < TPW; ++t) {
            float xv = xr0[(size_t)t * IN_D + k];
            xo0[(size_t)t * IN_D + k] = __float2half_rn(xv);
            acc[t][0] += xv * wa.x; acc[t][1] += xv * wa.y;
            acc[t][2] += xv * wa.z; acc[t][3] += xv * wa.w;
            acc[t][4] += xv * wb.x; acc[t][5] += xv * wb.y;
            acc[t][6] += xv * wb.z; acc[t][7] += xv * wb.w;
        }
    }

#pragma unroll
    for (int t = 0; t < TPW; ++t) {
#pragma unroll
        for (int e = 0; e < NEXP; ++e) {
            float v = acc[t][e];
            v += __shfl_xor_sync(0xFFFFFFFFu, v, 16);
            v += __shfl_xor_sync(0xFFFFFFFFu, v, 8);
            v += __shfl_xor_sync(0xFFFFFFFFu, v, 4);
            v += __shfl_xor_sync(0xFFFFFFFFu, v, 2);
            v += __shfl_xor_sync(0xFFFFFFFFu, v, 1);
            acc[t][e] = v + bg[e];
        }
        float m = acc[t][0];
#pragma unroll
        for (int e = 1; e < NEXP; ++e) m = fmaxf(m, acc[t][e]);
        float s = 0.f;
#pragma unroll
        for (int e = 0; e < NEXP; ++e) { acc[t][e] = expf(acc[t][e] - m); s += acc[t][e]; }
        float inv = 1.f / s;
        if (lane < NEXP)
            out[(size_t)B_TOK + (size_t)(tok0 + t) * NEXP + lane] = acc[t][lane] * inv;
    }
}

// ---------------------------------------------------------------------------
// GEMM config (PROVEN 1196us R8 config): CTA 128x128, 256 thr = 8 warps (2x4),
//   warp tile 64x32, 3-stage cp.async ring (32KB/stage), 96KB/CTA, 2 CTA/SM
// ---------------------------------------------------------------------------
#define G_STAGE 32768

#define CHUNK_MMA(acc_, sS_) do {                                              \
        _Pragma("unroll")                                                      \
        for (int k16_ = 0; k16_ < 4; ++k16_) {                                 \
            const uint32_t kx_ = (uint32_t)(k16_ << 5);                        \
            const uint32_t aA_ = ((sS_) + baseA0) ^ kx_;                       \
            const uint32_t bA_ = ((sS_) + baseB0) ^ kx_;                       \
            uint32_t af_[4][4], bf_[2][4];                                     \
            ldsm4(af_[0], aA_);                                                \
            ldsm4(af_[1], aA_ + 2048u);                                        \
            ldsm4(af_[2], aA_ + 4096u);                                        \
            ldsm4(af_[3], aA_ + 6144u);                                        \
            ldsm4(bf_[0], bA_);                                                \
            ldsm4(bf_[1], bA_ + 2048u);                                        \
            _Pragma("unroll")                                                  \
            for (int mf_ = 0; mf_ < 4; ++mf_)                                  \
                _Pragma("unroll")                                              \
                for (int nf_ = 0; nf_ < 4; ++nf_)                              \
                    mma16816((acc_)[mf_][nf_], af_[mf_],                       \
                             bf_[nf_ >> 1][nf_ & 1], bf_[nf_ >> 1][2 + (nf_ & 1)]); \
        }                                                                      \
    } while (0)

// ---------------------------------------------------------------------------
// Kernel 2: GEMM1 h1 = relu(x @ W1cat + b1)   (R8-exact)
// ---------------------------------------------------------------------------
__global__ __launch_bounds__(256, 2)
void gemm1_kernel(const float* __restrict__ b1) {
    extern __shared__ char smem[];
    const uint32_t sb = su32(smem);
    const int tid = threadIdx.x, lane = tid & 31, wid = tid >> 5;
    const int m0 = blockIdx.y * 128;
    const int n0 = blockIdx.x * 128;
    const int wm = wid >> 2, wn = wid & 3;   // warp grid 2 x 4

    const int r0 = tid >> 3, c0 = tid & 7;
    const uint32_t so0 = SWROW(r0, c0 * 16);
    const __half* gA0 = g_xh  + (size_t)(m0 + r0) * IN_D + c0 * 8;
    const __half* gB0 = g_w1t + (size_t)(n0 + r0) * IN_D + c0 * 8;

#define G1_LOAD(it_, s_) do {                                                  \
        const int k0_ = (it_) * KC;                                            \
        const uint32_t sA_ = sb + (s_) * G_STAGE;                              \
        const uint32_t sB_ = sA_ + 16384;                                      \
        _Pragma("unroll")                                                      \
        for (int i_ = 0; i_ < 4; ++i_)                                         \
            cpasync16(sA_ + so0 + i_ * 4096,                                   \
                      gA0 + (size_t)i_ * 32 * IN_D + k0_);                     \
        _Pragma("unroll")                                                      \
        for (int i_ = 0; i_ < 4; ++i_)                                         \
            cpasync16(sB_ + so0 + i_ * 4096,                                   \
                      gB0 + (size_t)i_ * 32 * IN_D + k0_);                     \
        CP_COMMIT();                                                           \
    } while (0)

    float acc[4][4][4];
#pragma unroll
    for (int i = 0; i < 4; ++i)
#pragma unroll
        for (int j = 0; j < 4; ++j)
#pragma unroll
            for (int q = 0; q < 4; ++q) acc[i][j][q] = 0.f;

    const int lrow = lane & 15;
    const int lcol = (lane >> 4) * 16;
    const uint32_t baseA0 = SWROW(wm * 64 + lrow, lcol);
    const uint32_t baseB0 = 16384u + SWROW(wn * 32 + lrow, lcol);

    const int NIT = IN_D / KC;   // 20
    G1_LOAD(0, 0);
    G1_LOAD(1, 1);

    int stage = 0;
    for (int it = 0; it < NIT; ++it) {
        CP_WAIT(1);
        __syncthreads();
        if (it + 2 < NIT) {
            int s2 = stage + 2; if (s2 >= 3) s2 -= 3;
            G1_LOAD(it + 2, s2);
        } else { CP_COMMIT(); }

        const uint32_t sS = sb + stage * G_STAGE;
        CHUNK_MMA(acc, sS);
        if (++stage == 3) stage = 0;
    }
#undef G1_LOAD

    // ---- epilogue: bias + relu -> fp16 -> g_h1 ----
    float2 bias[4];
#pragma unroll
    for (int nf = 0; nf < 4; ++nf) {
        int n = n0 + wn * 32 + nf * 8 + (lane & 3) * 2;
        bias[nf] = make_float2(b1[n], b1[n + 1]);
    }
#pragma unroll
    for (int mf = 0; mf < 4; ++mf) {
        int mA = m0 + wm * 64 + mf * 16 + (lane >> 2);
        __half* row0 = g_h1 + (size_t)mA * N_TOT;
        __half* row1 = row0 + (size_t)8 * N_TOT;
#pragma unroll
        for (int nf = 0; nf < 4; ++nf) {
            int n = n0 + wn * 32 + nf * 8 + (lane & 3) * 2;
            float v0 = fmaxf(acc[mf][nf][0] + bias[nf].x, 0.f);
            float v1 = fmaxf(acc[mf][nf][1] + bias[nf].y, 0.f);
            float v2 = fmaxf(acc[mf][nf][2] + bias[nf].x, 0.f);
            float v3 = fmaxf(acc[mf][nf][3] + bias[nf].y, 0.f);
            *reinterpret_cast<uint32_t*>(row0 + n) = packh(v0, v1);
            *reinterpret_cast<uint32_t*>(row1 + n) = packh(v2, v3);
        }
    }
}

// ---------------------------------------------------------------------------
// Kernel 3: GEMM2 + layer3 + gate-weighted sum -> predictions (R8-exact)
//   CTA 128(M) x 128(N=H2); 32 chunks = 8 experts x 4 k-chunks
// ---------------------------------------------------------------------------
__global__ __launch_bounds__(256, 2)
void gemm2_kernel(const float* __restrict__ b2, const float* __restrict__ W3,
                  const float* __restrict__ b3, float* __restrict__ out) {
    extern __shared__ char smem[];
    const uint32_t sb = su32(smem);
    float* s_part = reinterpret_cast<float*>(smem + 3 * G_STAGE); // [2][128][4]
    const int tid = threadIdx.x, lane = tid & 31, wid = tid >> 5;
    const int m0 = blockIdx.x * 128;
    const int wm = wid >> 2, wn = wid & 3;   // warp grid 2 x 4

    float predv = 0.f;

    const int r0 = tid >> 3, c0 = tid & 7;
    const uint32_t so0 = SWROW(r0, c0 * 16);
    const __half* gA0 = g_h1  + (size_t)(m0 + r0) * N_TOT + c0 * 8;
    const __half* gB0 = g_w2t + (size_t)r0 * HID1 + c0 * 8;

#define G2_LOAD(c_, s_) do {                                                   \
        const uint32_t sA_ = sb + (s_) * G_STAGE;                              \
        const uint32_t sB_ = sA_ + 16384;                                      \
        const int aoff_ = (c_) * KC;               /* (4e+kb)*64 == c*64 */    \
        const int boff_ = ((c_) >> 2) * (HID2 * HID1) + ((c_) & 3) * KC;       \
        _Pragma("unroll")                                                      \
        for (int i_ = 0; i_ < 4; ++i_)                                         \
            cpasync16(sA_ + so0 + i_ * 4096,                                   \
                      gA0 + (size_t)i_ * 32 * N_TOT + aoff_);                  \
        _Pragma("unroll")                                                      \
        for (int i_ = 0; i_ < 4; ++i_)                                         \
            cpasync16(sB_ + so0 + i_ * 4096,                                   \
                      gB0 + (size_t)i_ * 32 * HID1 + boff_);                   \
        CP_COMMIT();                                                           \
    } while (0)

    const int lrow = lane & 15;
    const int lcol = (lane >> 4) * 16;
    const uint32_t baseA0 = SWROW(wm * 64 + lrow, lcol);
    const uint32_t baseB0 = 16384u + SWROW(wn * 32 + lrow, lcol);

    G2_LOAD(0, 0);
    G2_LOAD(1, 1);

    float acc[4][4][4];
    int stage = 0;

    for (int c = 0; c < 32; ++c) {
        const int e = c >> 2, kb = c & 3;
        if (kb == 0) {
#pragma unroll
            for (int i = 0; i < 4; ++i)
#pragma unroll
                for (int j = 0; j < 4; ++j)
#pragma unroll
                    for (int q = 0; q < 4; ++q) acc[i][j][q] = 0.f;
        }

        CP_WAIT(1);
        __syncthreads();
        if (c + 2 < 32) {
            int s2 = stage + 2; if (s2 >= 3) s2 -= 3;
            G2_LOAD(c + 2, s2);
        } else { CP_COMMIT(); }

        const uint32_t sS = sb + stage * G_STAGE;
        CHUNK_MMA(acc, sS);
        if (++stage == 3) stage = 0;

        if (kb == 3) {
            // relu(h2 + b2) . W3 per row -> partials (double-buffered)
            float2 b2v[4], w3v[4];
#pragma unroll
            for (int nf = 0; nf < 4; ++nf) {
                int n = e * HID2 + wn * 32 + nf * 8 + (lane & 3) * 2;
                b2v[nf] = make_float2(b2[n], b2[n + 1]);
                w3v[nf] = make_float2(W3[n], W3[n + 1]);
            }
            float* part = s_part + (e & 1) * 512;
#pragma unroll
            for (int mf = 0; mf < 4; ++mf) {
#pragma unroll
                for (int h = 0; h < 2; ++h) {
                    float s = 0.f;
#pragma unroll
                    for (int nf = 0; nf < 4; ++nf) {
                        float hv0 = fmaxf(acc[mf][nf][h * 2 + 0] + b2v[nf].x, 0.f);
                        float hv1 = fmaxf(acc[mf][nf][h * 2 + 1] + b2v[nf].y, 0.f);
                        s += hv0 * w3v[nf].x + hv1 * w3v[nf].y;
                    }
                    s += __shfl_xor_sync(0xFFFFFFFFu, s, 1);
                    s += __shfl_xor_sync(0xFFFFFFFFu, s, 2);
                    if ((lane & 3) == 0) {
                        int m_local = wm * 64 + mf * 16 + h * 8 + (lane >> 2);
                        part[m_local * 4 + wn] = s;
                    }
                }
            }
            __syncthreads();
            if (tid < 128) {
                float dot = part[tid * 4 + 0] + part[tid * 4 + 1] +
                            part[tid * 4 + 2] + part[tid * 4 + 3];
                float g = out[(size_t)B_TOK + (size_t)(m0 + tid) * NEXP + e];
                predv += g * (dot + b3[e]);
            }
            // no trailing sync: next expert uses the other part buffer, and
            // chunk-top syncs separate reuse of this one
        }
    }
#undef G2_LOAD
    if (tid < 128) out[m0 + tid] = predv;
}

// ---------------------------------------------------------------------------
// Launch
// ---------------------------------------------------------------------------
extern "C" void kernel_launch(void* const* d_in, const int* in_sizes, int n_in,
                              void* d_out, int out_size) {
    const float* x  = (const float*)d_in[0];
    const float* W1 = (const float*)d_in[1];
    const float* b1 = (const float*)d_in[2];
    const float* W2 = (const float*)d_in[3];
    const float* b2 = (const float*)d_in[4];
    const float* W3 = (const float*)d_in[5];
    const float* b3 = (const float*)d_in[6];
    const float* Wg = (const float*)d_in[7];
    const float* bg = (const float*)d_in[8];
    float* out = (float*)d_out;

    const int SMEM1 = 3 * G_STAGE;            // 98304
    const int SMEM2 = 3 * G_STAGE + 4096;     // 102400
    cudaFuncSetAttribute(gemm1_kernel, cudaFuncAttributeMaxDynamicSharedMemorySize, SMEM1);
    cudaFuncSetAttribute(gemm2_kernel, cudaFuncAttributeMaxDynamicSharedMemorySize, SMEM2);

    // gate blocks: 65536 tokens / (8 warps * TPW tokens) = 2048
    init_kernel<<<PACK_BLOCKS + B_TOK / (8 * TPW), 256>>>(W1, W2, x, Wg, bg, out);
    gemm1_kernel<<<dim3(N_TOT / 128, B_TOK / 128), 256, SMEM1>>>(b1);
    gemm2_kernel<<<B_TOK / 128, 256, SMEM2>>>(b2, W3, b3, out);
}